// round 14
// baseline (speedup 1.0000x reference)
#include <cuda_runtime.h>
#include <stdint.h>

// out[i] = -cost[i, inputs[i]] * mask[i]
// cost: float32 [N, V], inputs: int32 [N], mask: float32 [N], out: float32 [N]
// N = 16384, V = 32000.
//
// FINAL (held, 5 samples). Scalar, guard-free, 128 threads x 128 CTAs.
//
// Identical-binary measurements: 4.70 / 6.66 / 4.70 / 6.56 / 6.21 us.
// Fast mode ~4.7us plus a slow band 6.2-6.9us; spread ~2us on constant code
// while all ncu counters stay flat (DRAM ~3%, issue 0.7%, 16 regs; even
// reported occupancy varies 6.7%-19.4% across identical runs). Variance is
// session state (DVFS/co-tenancy/placement), not kernel structure.
//
// Lever audit (all tried): kernel fusion (R3, -6us), int32-index shortcut
// (R4), bounds-check removal (R7), x2/x4 vectorization (R5/R6/R9 — neutral or
// worse), CTA shapes 32/128/256 thr x 64/128 CTAs. Per-element work is the
// algorithmic minimum: coalesced idx load -> dependent scattered gather ->
// mask load -> FMA -> coalesced store (~16B/element, no reuse, no fusible
// neighbor). Nothing remaining has predicted effect above measurement noise.

__global__ void __launch_bounds__(128, 1)
masked_nll_exact(const float* __restrict__ cost,
                 const int* __restrict__ idx,
                 const float* __restrict__ mask,
                 float* __restrict__ out,
                 unsigned v) {
    unsigned i = blockIdx.x * 128u + threadIdx.x;
    // Element offset fits in 32 bits: 16384*32000 + 31999 < 2^31.
    unsigned off = i * v + (unsigned)idx[i];
    out[i] = -__ldg(cost + off) * mask[i];
}

__global__ void __launch_bounds__(128, 1)
masked_nll_guarded(const float* __restrict__ cost,
                   const int* __restrict__ idx,
                   const float* __restrict__ mask,
                   float* __restrict__ out,
                   int n, unsigned v) {
    unsigned i = blockIdx.x * 128u + threadIdx.x;
    if (i >= (unsigned)n) return;
    unsigned off = i * v + (unsigned)idx[i];
    out[i] = -__ldg(cost + off) * mask[i];
}

extern "C" void kernel_launch(void* const* d_in, const int* in_sizes, int n_in,
                              void* d_out, int out_size) {
    const float* cost = (const float*)d_in[0];
    const int*   idx  = (const int*)d_in[1];
    const float* mask = (const float*)d_in[2];
    float*       out  = (float*)d_out;

    int n = in_sizes[1];                      // N = element count of inputs[]
    unsigned v = (unsigned)(in_sizes[0] / n); // V = cost elems / N

    const int threads = 128;
    if (n % threads == 0) {
        masked_nll_exact<<<n / threads, threads>>>(cost, idx, mask, out, v);
    } else {
        masked_nll_guarded<<<(n + threads - 1) / threads, threads>>>(
            cost, idx, mask, out, n, v);
    }
}

// round 15
// speedup vs baseline: 1.0700x; 1.0700x over previous
#include <cuda_runtime.h>
#include <stdint.h>

// out[i] = -cost[i, inputs[i]] * mask[i]
// cost: float32 [N, V], inputs: int32 [N], mask: float32 [N], out: float32 [N]
// N = 16384, V = 32000.
//
// FINAL (held, 6 samples). Scalar, guard-free, 128 threads x 128 CTAs.
//
// Identical-binary measurements: 4.70 / 6.66 / 4.70 / 6.56 / 6.21 / 6.85 us.
// Fast mode ~4.7us (~1/3 of sessions), slow band 6.2-6.9us (~2/3). All ncu
// counters invariant across draws (DRAM ~3%, issue 0.7%, 16 regs, one wave);
// the spread is session state (DVFS/co-tenancy/placement), not kernel
// structure — changing code to chase it would be fitting noise.
//
// Lever audit (exhaustive for this op): node fusion (R3, -6us), int32-index
// shortcut (R4), bounds-check removal (R7, kept), x2/x4 vectorization
// (R5/R6/R9 — neutral or worse), CTA shapes 32/128/256 thr x 64/128 CTAs.
// Per-element work is the algorithmic minimum: coalesced idx load ->
// dependent scattered gather -> mask load -> FMA -> coalesced store
// (~16B/element, zero reuse, no fusible neighbor). PDL / persistence / TMA /
// clusters are inapplicable to a single-node elementwise gather.

__global__ void __launch_bounds__(128, 1)
masked_nll_exact(const float* __restrict__ cost,
                 const int* __restrict__ idx,
                 const float* __restrict__ mask,
                 float* __restrict__ out,
                 unsigned v) {
    unsigned i = blockIdx.x * 128u + threadIdx.x;
    // Element offset fits in 32 bits: 16384*32000 + 31999 < 2^31.
    unsigned off = i * v + (unsigned)idx[i];
    out[i] = -__ldg(cost + off) * mask[i];
}

__global__ void __launch_bounds__(128, 1)
masked_nll_guarded(const float* __restrict__ cost,
                   const int* __restrict__ idx,
                   const float* __restrict__ mask,
                   float* __restrict__ out,
                   int n, unsigned v) {
    unsigned i = blockIdx.x * 128u + threadIdx.x;
    if (i >= (unsigned)n) return;
    unsigned off = i * v + (unsigned)idx[i];
    out[i] = -__ldg(cost + off) * mask[i];
}

extern "C" void kernel_launch(void* const* d_in, const int* in_sizes, int n_in,
                              void* d_out, int out_size) {
    const float* cost = (const float*)d_in[0];
    const int*   idx  = (const int*)d_in[1];
    const float* mask = (const float*)d_in[2];
    float*       out  = (float*)d_out;

    int n = in_sizes[1];                      // N = element count of inputs[]
    unsigned v = (unsigned)(in_sizes[0] / n); // V = cost elems / N

    const int threads = 128;
    if (n % threads == 0) {
        masked_nll_exact<<<n / threads, threads>>>(cost, idx, mask, out, v);
    } else {
        masked_nll_guarded<<<(n + threads - 1) / threads, threads>>>(
            cost, idx, mask, out, n, v);
    }
}